// round 3
// baseline (speedup 1.0000x reference)
#include <cuda_runtime.h>
#include <math.h>

#define Bsz  4096
#define Din  512
#define Hd   1024
#define KE   8
#define Oo   256
#define NHh  4
#define HDim 256
#define EPSv 1e-5f

// ---------------- scratch (device globals; no allocations allowed) ----------
__device__ float g_gi[(size_t)Bsz * KE * 3 * Hd];   // (B, K, 3H)
__device__ float g_gh[(size_t)Bsz * KE * 3 * Hd];   // (B, K, 3H)
__device__ float g_query[(size_t)Bsz * Hd];
__device__ float g_q[(size_t)Bsz * Hd];
__device__ float g_kmat[(size_t)Bsz * KE * Hd];
__device__ float g_vmat[(size_t)Bsz * KE * Hd];
__device__ float g_ctx[(size_t)Bsz * Hd];
__device__ float g_attnout[(size_t)Bsz * Hd];
__device__ float g_context[(size_t)Bsz * Hd];
__device__ float g_mixed[(size_t)Bsz * Hd];

// ---------------- generic TN SGEMM: C[m,n] = sum_k A[m,k]*B[n,k] + bias[n] ---
// A: (M, Kd) row-major w/ stride lda ; B: (N, Kd) row-major w/ stride ldb
// grid = (N/128, M/128, batch); 256 threads; 8x8 micro-tile.
__global__ __launch_bounds__(256, 2)
void sgemm_tn(const float* __restrict__ A, const float* __restrict__ Bm,
              const float* __restrict__ bias, float* __restrict__ C,
              int Kd, int lda, int ldb, int ldc,
              long aBat, long bBat, long cBat, long biasBat)
{
    const int bz = blockIdx.z;
    A  += (long)bz * aBat;
    Bm += (long)bz * bBat;
    C  += (long)bz * cBat;
    const float* biasp = bias ? bias + (long)bz * biasBat : nullptr;

    __shared__ float As[16][132];   // +4 pad: kills 4-way transpose-store conflicts
    __shared__ float Bs[16][132];

    const int tid = threadIdx.x;
    const int tx  = tid & 15;        // 0..15  -> N direction
    const int ty  = tid >> 4;        // 0..15  -> M direction
    const int lr  = tid >> 2;        // 0..63  load row
    const int lc  = (tid & 3) << 2;  // 0,4,8,12 load col (k)

    const float* Ap = A  + (long)(blockIdx.y * 128 + lr) * lda + lc;
    const float* Bp = Bm + (long)(blockIdx.x * 128 + lr) * ldb + lc;

    float acc[8][8];
    #pragma unroll
    for (int i = 0; i < 8; i++)
        #pragma unroll
        for (int j = 0; j < 8; j++) acc[i][j] = 0.0f;

    for (int k0 = 0; k0 < Kd; k0 += 16) {
        float4 a0 = *(const float4*)(Ap);
        float4 a1 = *(const float4*)(Ap + (long)64 * lda);
        float4 b0 = *(const float4*)(Bp);
        float4 b1 = *(const float4*)(Bp + (long)64 * ldb);

        As[lc + 0][lr] = a0.x; As[lc + 1][lr] = a0.y;
        As[lc + 2][lr] = a0.z; As[lc + 3][lr] = a0.w;
        As[lc + 0][lr + 64] = a1.x; As[lc + 1][lr + 64] = a1.y;
        As[lc + 2][lr + 64] = a1.z; As[lc + 3][lr + 64] = a1.w;
        Bs[lc + 0][lr] = b0.x; Bs[lc + 1][lr] = b0.y;
        Bs[lc + 2][lr] = b0.z; Bs[lc + 3][lr] = b0.w;
        Bs[lc + 0][lr + 64] = b1.x; Bs[lc + 1][lr + 64] = b1.y;
        Bs[lc + 2][lr + 64] = b1.z; Bs[lc + 3][lr + 64] = b1.w;
        __syncthreads();

        #pragma unroll
        for (int kk = 0; kk < 16; kk++) {
            float ar[8], br[8];
            *(float4*)&ar[0] = *(const float4*)&As[kk][ty * 8];
            *(float4*)&ar[4] = *(const float4*)&As[kk][ty * 8 + 4];
            *(float4*)&br[0] = *(const float4*)&Bs[kk][tx * 8];
            *(float4*)&br[4] = *(const float4*)&Bs[kk][tx * 8 + 4];
            #pragma unroll
            for (int i = 0; i < 8; i++)
                #pragma unroll
                for (int j = 0; j < 8; j++)
                    acc[i][j] += ar[i] * br[j];
        }
        __syncthreads();
        Ap += 16; Bp += 16;
    }

    const int rowC = blockIdx.y * 128 + ty * 8;
    const int colC = blockIdx.x * 128 + tx * 8;
    float bv[8];
    #pragma unroll
    for (int j = 0; j < 8; j++) bv[j] = biasp ? biasp[colC + j] : 0.0f;
    #pragma unroll
    for (int i = 0; i < 8; i++) {
        float4 o0, o1;
        o0.x = acc[i][0] + bv[0]; o0.y = acc[i][1] + bv[1];
        o0.z = acc[i][2] + bv[2]; o0.w = acc[i][3] + bv[3];
        o1.x = acc[i][4] + bv[4]; o1.y = acc[i][5] + bv[5];
        o1.z = acc[i][6] + bv[6]; o1.w = acc[i][7] + bv[7];
        float* cp = C + (long)(rowC + i) * ldc + colC;
        *(float4*)(cp)     = o0;
        *(float4*)(cp + 4) = o1;
    }
}

// ---------------- GRU pointwise + per-expert LayerNorm -----------------------
// one block per (b,k) row of H=1024 ; 256 threads x 4 elements
__global__ void gru_ln_kernel(const float* __restrict__ gi, const float* __restrict__ gh,
                              const float* __restrict__ h_prev,
                              const float* __restrict__ ln_g, const float* __restrict__ ln_b,
                              float* __restrict__ h_new)
{
    const int bk = blockIdx.x;
    const int k  = bk & (KE - 1);
    const long giBase = (long)bk * (3 * Hd);
    const long hBase  = (long)bk * Hd;
    const float* gir = gi + giBase;
    const float* ghr = gh + giBase;
    const float* hp  = h_prev + hBase;

    float vals[4];
    float s = 0.f, ss = 0.f;
    #pragma unroll
    for (int t = 0; t < 4; t++) {
        int h = threadIdx.x + t * 256;
        float ir = gir[h],          hr = ghr[h];
        float iz = gir[Hd + h],     hz = ghr[Hd + h];
        float inn = gir[2 * Hd + h], hn = ghr[2 * Hd + h];
        float r = 1.f / (1.f + expf(-(ir + hr)));
        float z = 1.f / (1.f + expf(-(iz + hz)));
        float n = tanhf(inn + r * hn);
        float hv = (1.f - z) * n + z * hp[h];
        vals[t] = hv; s += hv; ss += hv * hv;
    }
    __shared__ float red[16];
    #pragma unroll
    for (int o = 16; o; o >>= 1) {
        s  += __shfl_xor_sync(0xffffffffu, s, o);
        ss += __shfl_xor_sync(0xffffffffu, ss, o);
    }
    int w = threadIdx.x >> 5;
    if ((threadIdx.x & 31) == 0) { red[w] = s; red[8 + w] = ss; }
    __syncthreads();
    s = 0.f; ss = 0.f;
    #pragma unroll
    for (int i = 0; i < 8; i++) { s += red[i]; ss += red[8 + i]; }
    float mean = s * (1.f / Hd);
    float var  = ss * (1.f / Hd) - mean * mean;
    float rstd = rsqrtf(var + EPSv);
    #pragma unroll
    for (int t = 0; t < 4; t++) {
        int h = threadIdx.x + t * 256;
        h_new[hBase + h] = (vals[t] - mean) * rstd * ln_g[k * Hd + h] + ln_b[k * Hd + h];
    }
}

// ---------------- attention over K=8 expert states ---------------------------
// one block per (b, head); 256 threads (= HD). Warp w computes score for expert w.
__global__ void attn_kernel(const float* __restrict__ q, const float* __restrict__ kmat,
                            const float* __restrict__ vmat, float* __restrict__ ctx)
{
    const int b = blockIdx.x >> 2;   // NH = 4
    const int n = blockIdx.x & 3;
    const int tid = threadIdx.x;
    const int lane = tid & 31, w = tid >> 5;
    __shared__ float sc[KE];
    const float* qp = q + (long)b * Hd + n * HDim;
    {
        const float* kp = kmat + (long)b * KE * Hd + (long)w * Hd + n * HDim;
        float s = 0.f;
        #pragma unroll
        for (int d = lane; d < HDim; d += 32) s += qp[d] * kp[d];
        #pragma unroll
        for (int o = 16; o; o >>= 1) s += __shfl_xor_sync(0xffffffffu, s, o);
        if (lane == 0) sc[w] = s * (1.0f / 16.0f);   // 1/sqrt(HD)
    }
    __syncthreads();
    float e[KE], m = -1e30f;
    #pragma unroll
    for (int k = 0; k < KE; k++) m = fmaxf(m, sc[k]);
    float sum = 0.f;
    #pragma unroll
    for (int k = 0; k < KE; k++) { e[k] = expf(sc[k] - m); sum += e[k]; }
    float inv = 1.f / sum;
    float acc = 0.f;
    const float* vb = vmat + (long)b * KE * Hd + n * HDim + tid;
    #pragma unroll
    for (int k = 0; k < KE; k++) acc += e[k] * inv * vb[(long)k * Hd];
    ctx[(long)b * Hd + n * HDim + tid] = acc;
}

// ---------------- residual add + LayerNorm -----------------------------------
__global__ void add_ln_kernel(const float* __restrict__ a, const float* __restrict__ bvec,
                              const float* __restrict__ g, const float* __restrict__ be,
                              float* __restrict__ out)
{
    const int b = blockIdx.x;
    const long base = (long)b * Hd;
    float vals[4]; float s = 0.f, ss = 0.f;
    #pragma unroll
    for (int t = 0; t < 4; t++) {
        int h = threadIdx.x + t * 256;
        float v = a[base + h] + bvec[base + h];
        vals[t] = v; s += v; ss += v * v;
    }
    __shared__ float red[16];
    #pragma unroll
    for (int o = 16; o; o >>= 1) {
        s  += __shfl_xor_sync(0xffffffffu, s, o);
        ss += __shfl_xor_sync(0xffffffffu, ss, o);
    }
    int w = threadIdx.x >> 5;
    if ((threadIdx.x & 31) == 0) { red[w] = s; red[8 + w] = ss; }
    __syncthreads();
    s = 0.f; ss = 0.f;
    #pragma unroll
    for (int i = 0; i < 8; i++) { s += red[i]; ss += red[8 + i]; }
    float mean = s * (1.f / Hd);
    float rstd = rsqrtf(ss * (1.f / Hd) - mean * mean + EPSv);
    #pragma unroll
    for (int t = 0; t < 4; t++) {
        int h = threadIdx.x + t * 256;
        out[base + h] = (vals[t] - mean) * rstd * g[h] + be[h];
    }
}

// ---------------- gate logits + softmax + expert mix -------------------------
// one block per b; 8 warps, warp w computes logit w; then all mix h_new.
__global__ void gate_mix_kernel(const float* __restrict__ context, const float* __restrict__ W_gate,
                                const float* __restrict__ b_gate, const float* __restrict__ h_new,
                                float* __restrict__ logits_out, float* __restrict__ gt_out,
                                float* __restrict__ mixed)
{
    const int b = blockIdx.x;
    const int tid = threadIdx.x, lane = tid & 31, w = tid >> 5;
    __shared__ float sl[KE];
    const float* cr = context + (long)b * Hd;
    {
        const float* wg = W_gate + (long)w * Hd;
        float s = 0.f;
        for (int h = lane; h < Hd; h += 32) s += cr[h] * wg[h];
        #pragma unroll
        for (int o = 16; o; o >>= 1) s += __shfl_xor_sync(0xffffffffu, s, o);
        if (lane == 0) sl[w] = s + b_gate[w];
    }
    __syncthreads();
    float lg[KE], m = -1e30f;
    #pragma unroll
    for (int k = 0; k < KE; k++) { lg[k] = sl[k]; m = fmaxf(m, lg[k]); }
    float e[KE], sum = 0.f;
    #pragma unroll
    for (int k = 0; k < KE; k++) { e[k] = expf(lg[k] - m); sum += e[k]; }
    float inv = 1.f / sum;
    if (tid < KE) {
        logits_out[(long)b * KE + tid] = lg[tid];
        gt_out[(long)b * KE + tid]     = e[tid] * inv;
    }
    const float* hb = h_new + (long)b * KE * Hd;
    #pragma unroll
    for (int t = 0; t < 4; t++) {
        int h = tid + t * 256;
        float acc = 0.f;
        #pragma unroll
        for (int k = 0; k < KE; k++) acc += e[k] * inv * hb[(long)k * Hd + h];
        mixed[(long)b * Hd + h] = acc;
    }
}

// ---------------- host orchestration -----------------------------------------
static void launch_gemm(const float* A, const float* Bm, const float* bias, float* C,
                        int M, int N, int Kd, int lda, int ldb, int ldc,
                        int batch, long aBat, long bBat, long cBat, long biasBat)
{
    dim3 grid(N / 128, M / 128, batch);
    sgemm_tn<<<grid, 256>>>(A, Bm, bias, C, Kd, lda, ldb, ldc, aBat, bBat, cBat, biasBat);
}

extern "C" void kernel_launch(void* const* d_in, const int* in_sizes, int n_in,
                              void* d_out, int out_size)
{
    const float* x_t     = (const float*)d_in[0];
    const float* h_prev  = (const float*)d_in[1];
    const float* W_ih    = (const float*)d_in[2];
    const float* W_hh    = (const float*)d_in[3];
    const float* b_ih    = (const float*)d_in[4];
    const float* b_hh    = (const float*)d_in[5];
    const float* ln_g    = (const float*)d_in[6];
    const float* ln_b    = (const float*)d_in[7];
    const float* Wq_proj = (const float*)d_in[8];
    const float* bq_proj = (const float*)d_in[9];
    const float* W_q     = (const float*)d_in[10];
    const float* W_k     = (const float*)d_in[11];
    const float* W_v     = (const float*)d_in[12];
    const float* b_q     = (const float*)d_in[13];
    const float* b_k     = (const float*)d_in[14];
    const float* b_v     = (const float*)d_in[15];
    const float* W_o     = (const float*)d_in[16];
    const float* b_o     = (const float*)d_in[17];
    const float* aln_g   = (const float*)d_in[18];
    const float* aln_b   = (const float*)d_in[19];
    const float* W_gate  = (const float*)d_in[20];
    const float* b_gate  = (const float*)d_in[21];
    const float* W_read  = (const float*)d_in[22];
    const float* b_read  = (const float*)d_in[23];

    float* out    = (float*)d_out;
    float* h_new  = out;                                   // (B,K,H)
    float* y_hat  = out + (long)Bsz * KE * Hd;             // (B,O)
    float* g_t    = y_hat + (long)Bsz * Oo;                // (B,K)
    float* logits = g_t + (long)Bsz * KE;                  // (B,K)

    float *gi, *gh, *query, *qm, *kmat, *vmat, *ctx, *attnout, *contextb, *mixed;
    cudaGetSymbolAddress((void**)&gi, g_gi);
    cudaGetSymbolAddress((void**)&gh, g_gh);
    cudaGetSymbolAddress((void**)&query, g_query);
    cudaGetSymbolAddress((void**)&qm, g_q);
    cudaGetSymbolAddress((void**)&kmat, g_kmat);
    cudaGetSymbolAddress((void**)&vmat, g_vmat);
    cudaGetSymbolAddress((void**)&ctx, g_ctx);
    cudaGetSymbolAddress((void**)&attnout, g_attnout);
    cudaGetSymbolAddress((void**)&contextb, g_context);
    cudaGetSymbolAddress((void**)&mixed, g_mixed);

    // 1) gi = x_t @ W_ih^T + b_ih          (4096 x 24576 x 512)
    launch_gemm(x_t, W_ih, b_ih, gi, Bsz, KE * 3 * Hd, Din,
                Din, Din, KE * 3 * Hd, 1, 0, 0, 0, 0);
    // 2) gh[k] = h_prev[:,k,:] @ W_hh[k]^T + b_hh[k]   (batched over K)
    launch_gemm(h_prev, W_hh, b_hh, gh, Bsz, 3 * Hd, Hd,
                KE * Hd, Hd, KE * 3 * Hd, KE,
                (long)Hd, (long)3 * Hd * Hd, (long)3 * Hd, (long)3 * Hd);
    // 3) GRU pointwise + per-expert LN -> h_new (into d_out)
    gru_ln_kernel<<<Bsz * KE, 256>>>(gi, gh, h_prev, ln_g, ln_b, h_new);
    // 4) query = x_t @ Wq_proj^T + bq_proj
    launch_gemm(x_t, Wq_proj, bq_proj, query, Bsz, Hd, Din,
                Din, Din, Hd, 1, 0, 0, 0, 0);
    // 5) q = query @ W_q^T + b_q
    launch_gemm(query, W_q, b_q, qm, Bsz, Hd, Hd, Hd, Hd, Hd, 1, 0, 0, 0, 0);
    // 6) kmat = h_new @ W_k^T + b_k     (32768 x 1024 x 1024)
    launch_gemm(h_new, W_k, b_k, kmat, Bsz * KE, Hd, Hd, Hd, Hd, Hd, 1, 0, 0, 0, 0);
    // 7) vmat = h_new @ W_v^T + b_v
    launch_gemm(h_new, W_v, b_v, vmat, Bsz * KE, Hd, Hd, Hd, Hd, Hd, 1, 0, 0, 0, 0);
    // 8) attention -> ctx
    attn_kernel<<<Bsz * NHh, 256>>>(qm, kmat, vmat, ctx);
    // 9) attn_out = ctx @ W_o^T + b_o
    launch_gemm(ctx, W_o, b_o, attnout, Bsz, Hd, Hd, Hd, Hd, Hd, 1, 0, 0, 0, 0);
    // 10) context = LN(query + attn_out)
    add_ln_kernel<<<Bsz, 256>>>(query, attnout, aln_g, aln_b, contextb);
    // 11) gate logits + softmax + mix
    gate_mix_kernel<<<Bsz, 256>>>(contextb, W_gate, b_gate, h_new, logits, g_t, mixed);
    // 12) y_hat = mixed @ W_read^T + b_read
    launch_gemm(mixed, W_read, b_read, y_hat, Bsz, Oo, Hd, Hd, Hd, Oo, 1, 0, 0, 0, 0);
}

// round 7
// speedup vs baseline: 2.6584x; 2.6584x over previous
#include <cuda_runtime.h>
#include <math.h>
#include <stdint.h>

#define Bsz  4096
#define Din  512
#define Hd   1024
#define KE   8
#define Oo   256
#define NHh  4
#define HDim 256
#define EPSv 1e-5f

// ---------------- scratch (device globals; no allocations allowed) ----------
__device__ float g_gi[(size_t)Bsz * KE * 3 * Hd];   // (B, K, 3H)
__device__ float g_gh[(size_t)Bsz * KE * 3 * Hd];   // (B, K, 3H)
__device__ float g_query[(size_t)Bsz * Hd];
__device__ float g_q[(size_t)Bsz * Hd];
__device__ float g_kmat[(size_t)Bsz * KE * Hd];
__device__ float g_vmat[(size_t)Bsz * KE * Hd];
__device__ float g_ctx[(size_t)Bsz * Hd];
__device__ float g_attnout[(size_t)Bsz * Hd];
__device__ float g_context[(size_t)Bsz * Hd];
__device__ float g_mixed[(size_t)Bsz * Hd];

// ---------------- helpers ----------------------------------------------------
__device__ __forceinline__ float to_tf32(float x) {
    float r; asm("cvt.rna.tf32.f32 %0, %1;" : "=f"(r) : "f"(x)); return r;
}
__device__ __forceinline__ void mma16n8k8(float* c, const uint32_t* a, const uint32_t* b) {
    asm volatile("mma.sync.aligned.m16n8k8.row.col.f32.tf32.tf32.f32 "
        "{%0,%1,%2,%3}, {%4,%5,%6,%7}, {%8,%9}, {%0,%1,%2,%3};"
        : "+f"(c[0]), "+f"(c[1]), "+f"(c[2]), "+f"(c[3])
        : "r"(a[0]), "r"(a[1]), "r"(a[2]), "r"(a[3]), "r"(b[0]), "r"(b[1]));
}

// ================= tf32 mma.sync TN GEMM =====================================
// C[m,n] = sum_k A[m,k]*B[n,k] + bias[n]
// Block 128x128, K-chunk 32, 256 threads (8 warps: 2M x 4N, warp tile 64x32).
// Smem stage: A 128x32 (stride 36), B 128x32 (stride 36); double buffered.
#define STG_W   4608                       // 128*36 words per matrix-stage
#define SMEMW   (4 * STG_W)                // A0 A1 B0 B1
#define SMEMB   (SMEMW * 4)                // 73728 bytes

__global__ __launch_bounds__(256, 1)
void mma_tn(const float* __restrict__ A, const float* __restrict__ Bm,
            const float* __restrict__ bias, float* __restrict__ C,
            int Kd, int lda, int ldb, int ldc,
            long aBat, long bBat, long cBat, long biasBat)
{
    extern __shared__ float smf[];
    const int tid  = threadIdx.x;
    const int wid  = tid >> 5;
    const int lane = tid & 31;
    const int warpM = wid & 1;        // 0..1  (64 rows each)
    const int warpN = wid >> 1;       // 0..3  (32 cols each)
    const int r = lane >> 2;          // 0..7
    const int q = lane & 3;           // 0..3

    const int bz = blockIdx.z;
    A  += (long)bz * aBat;
    Bm += (long)bz * bBat;
    C  += (long)bz * cBat;
    const float* biasp = bias ? bias + (long)bz * biasBat : nullptr;

    const int rowBase = blockIdx.y * 128;
    const int colBase = blockIdx.x * 128;

    const int lrow = tid >> 3;        // 0..31 -> covers 128 rows via i*32
    const int lc4  = (tid & 7) * 4;   // 0,4,...,28

    float4 ar[4], br[4];

    // LDG one 32-wide K chunk into registers (A: rows rowBase+, B: rows colBase+)
    auto ldg_chunk = [&](int k0) {
        #pragma unroll
        for (int i = 0; i < 4; i++) {
            int row = lrow + i * 32;
            ar[i] = *(const float4*)(A  + (long)(rowBase + row) * lda + k0 + lc4);
            br[i] = *(const float4*)(Bm + (long)(colBase + row) * ldb + k0 + lc4);
        }
    };
    // rna-round to tf32 and store to smem stage s
    auto sts_chunk = [&](int s) {
        float* as = smf + s * STG_W;
        float* bs = smf + 2 * STG_W + s * STG_W;
        #pragma unroll
        for (int i = 0; i < 4; i++) {
            int row = lrow + i * 32;
            float4 v = ar[i];
            v.x = to_tf32(v.x); v.y = to_tf32(v.y); v.z = to_tf32(v.z); v.w = to_tf32(v.w);
            *(float4*)(as + row * 36 + lc4) = v;
            float4 w = br[i];
            w.x = to_tf32(w.x); w.y = to_tf32(w.y); w.z = to_tf32(w.z); w.w = to_tf32(w.w);
            *(float4*)(bs + row * 36 + lc4) = w;
        }
    };

    float acc[4][4][4];
    #pragma unroll
    for (int mt = 0; mt < 4; mt++)
        #pragma unroll
        for (int nt = 0; nt < 4; nt++)
            #pragma unroll
            for (int j = 0; j < 4; j++) acc[mt][nt][j] = 0.0f;

    const int NC = Kd >> 5;

    ldg_chunk(0);
    sts_chunk(0);
    __syncthreads();

    for (int c = 0; c < NC; c++) {
        const int s = c & 1;
        if (c + 1 < NC) ldg_chunk((c + 1) * 32);

        const float* as = smf + s * STG_W + (warpM * 64) * 36;
        const float* bs = smf + 2 * STG_W + s * STG_W + (warpN * 32) * 36;

        #pragma unroll
        for (int ks = 0; ks < 4; ks++) {
            const int k0 = ks * 8;
            uint32_t afr[4][4], bfr[4][2];
            #pragma unroll
            for (int mt = 0; mt < 4; mt++) {
                const float* ap = as + (mt * 16 + r) * 36 + k0 + q;
                afr[mt][0] = __float_as_uint(ap[0]);
                afr[mt][1] = __float_as_uint(ap[8 * 36]);
                afr[mt][2] = __float_as_uint(ap[4]);
                afr[mt][3] = __float_as_uint(ap[8 * 36 + 4]);
            }
            #pragma unroll
            for (int nt = 0; nt < 4; nt++) {
                const float* bp = bs + (nt * 8 + r) * 36 + k0 + q;
                bfr[nt][0] = __float_as_uint(bp[0]);
                bfr[nt][1] = __float_as_uint(bp[4]);
            }
            #pragma unroll
            for (int mt = 0; mt < 4; mt++)
                #pragma unroll
                for (int nt = 0; nt < 4; nt++)
                    mma16n8k8(acc[mt][nt], afr[mt], bfr[nt]);
        }

        if (c + 1 < NC) {
            __syncthreads();
            sts_chunk((c + 1) & 1);
            __syncthreads();
        }
    }

    // ---- epilogue: acc -> C (+bias) ----
    #pragma unroll
    for (int mt = 0; mt < 4; mt++) {
        const int row = rowBase + warpM * 64 + mt * 16 + r;
        #pragma unroll
        for (int nt = 0; nt < 4; nt++) {
            const int col = colBase + warpN * 32 + nt * 8 + q * 2;
            float b0 = 0.f, b1 = 0.f;
            if (biasp) { b0 = biasp[col]; b1 = biasp[col + 1]; }
            float2 v0, v1;
            v0.x = acc[mt][nt][0] + b0; v0.y = acc[mt][nt][1] + b1;
            v1.x = acc[mt][nt][2] + b0; v1.y = acc[mt][nt][3] + b1;
            *(float2*)(C + (long)row * ldc + col)       = v0;
            *(float2*)(C + (long)(row + 8) * ldc + col) = v1;
        }
    }
}

// ---------------- GRU pointwise + per-expert LayerNorm -----------------------
__global__ void gru_ln_kernel(const float* __restrict__ gi, const float* __restrict__ gh,
                              const float* __restrict__ h_prev,
                              const float* __restrict__ ln_g, const float* __restrict__ ln_b,
                              float* __restrict__ h_new)
{
    const int bk = blockIdx.x;
    const int k  = bk & (KE - 1);
    const long giBase = (long)bk * (3 * Hd);
    const long hBase  = (long)bk * Hd;
    const float* gir = gi + giBase;
    const float* ghr = gh + giBase;
    const float* hp  = h_prev + hBase;

    float vals[4];
    float s = 0.f, ss = 0.f;
    #pragma unroll
    for (int t = 0; t < 4; t++) {
        int h = threadIdx.x + t * 256;
        float ir = gir[h],           hr = ghr[h];
        float iz = gir[Hd + h],      hz = ghr[Hd + h];
        float inn = gir[2 * Hd + h], hn = ghr[2 * Hd + h];
        float r = 1.f / (1.f + expf(-(ir + hr)));
        float z = 1.f / (1.f + expf(-(iz + hz)));
        float n = tanhf(inn + r * hn);
        float hv = (1.f - z) * n + z * hp[h];
        vals[t] = hv; s += hv; ss += hv * hv;
    }
    __shared__ float red[16];
    #pragma unroll
    for (int o = 16; o; o >>= 1) {
        s  += __shfl_xor_sync(0xffffffffu, s, o);
        ss += __shfl_xor_sync(0xffffffffu, ss, o);
    }
    int w = threadIdx.x >> 5;
    if ((threadIdx.x & 31) == 0) { red[w] = s; red[8 + w] = ss; }
    __syncthreads();
    s = 0.f; ss = 0.f;
    #pragma unroll
    for (int i = 0; i < 8; i++) { s += red[i]; ss += red[8 + i]; }
    float mean = s * (1.f / Hd);
    float var  = ss * (1.f / Hd) - mean * mean;
    float rstd = rsqrtf(var + EPSv);
    #pragma unroll
    for (int t = 0; t < 4; t++) {
        int h = threadIdx.x + t * 256;
        h_new[hBase + h] = (vals[t] - mean) * rstd * ln_g[k * Hd + h] + ln_b[k * Hd + h];
    }
}

// ---------------- attention over K=8 expert states ---------------------------
__global__ void attn_kernel(const float* __restrict__ q, const float* __restrict__ kmat,
                            const float* __restrict__ vmat, float* __restrict__ ctx)
{
    const int b = blockIdx.x >> 2;
    const int n = blockIdx.x & 3;
    const int tid = threadIdx.x;
    const int lane = tid & 31, w = tid >> 5;
    __shared__ float sc[KE];
    const float* qp = q + (long)b * Hd + n * HDim;
    {
        const float* kp = kmat + (long)b * KE * Hd + (long)w * Hd + n * HDim;
        float s = 0.f;
        #pragma unroll
        for (int d = lane; d < HDim; d += 32) s += qp[d] * kp[d];
        #pragma unroll
        for (int o = 16; o; o >>= 1) s += __shfl_xor_sync(0xffffffffu, s, o);
        if (lane == 0) sc[w] = s * (1.0f / 16.0f);
    }
    __syncthreads();
    float e[KE], m = -1e30f;
    #pragma unroll
    for (int k = 0; k < KE; k++) m = fmaxf(m, sc[k]);
    float sum = 0.f;
    #pragma unroll
    for (int k = 0; k < KE; k++) { e[k] = expf(sc[k] - m); sum += e[k]; }
    float inv = 1.f / sum;
    float acc = 0.f;
    const float* vb = vmat + (long)b * KE * Hd + n * HDim + tid;
    #pragma unroll
    for (int k = 0; k < KE; k++) acc += e[k] * inv * vb[(long)k * Hd];
    ctx[(long)b * Hd + n * HDim + tid] = acc;
}

// ---------------- residual add + LayerNorm -----------------------------------
__global__ void add_ln_kernel(const float* __restrict__ a, const float* __restrict__ bvec,
                              const float* __restrict__ g, const float* __restrict__ be,
                              float* __restrict__ out)
{
    const int b = blockIdx.x;
    const long base = (long)b * Hd;
    float vals[4]; float s = 0.f, ss = 0.f;
    #pragma unroll
    for (int t = 0; t < 4; t++) {
        int h = threadIdx.x + t * 256;
        float v = a[base + h] + bvec[base + h];
        vals[t] = v; s += v; ss += v * v;
    }
    __shared__ float red[16];
    #pragma unroll
    for (int o = 16; o; o >>= 1) {
        s  += __shfl_xor_sync(0xffffffffu, s, o);
        ss += __shfl_xor_sync(0xffffffffu, ss, o);
    }
    int w = threadIdx.x >> 5;
    if ((threadIdx.x & 31) == 0) { red[w] = s; red[8 + w] = ss; }
    __syncthreads();
    s = 0.f; ss = 0.f;
    #pragma unroll
    for (int i = 0; i < 8; i++) { s += red[i]; ss += red[8 + i]; }
    float mean = s * (1.f / Hd);
    float rstd = rsqrtf(ss * (1.f / Hd) - mean * mean + EPSv);
    #pragma unroll
    for (int t = 0; t < 4; t++) {
        int h = threadIdx.x + t * 256;
        out[base + h] = (vals[t] - mean) * rstd * g[h] + be[h];
    }
}

// ---------------- gate logits + softmax + expert mix -------------------------
__global__ void gate_mix_kernel(const float* __restrict__ context, const float* __restrict__ W_gate,
                                const float* __restrict__ b_gate, const float* __restrict__ h_new,
                                float* __restrict__ logits_out, float* __restrict__ gt_out,
                                float* __restrict__ mixed)
{
    const int b = blockIdx.x;
    const int tid = threadIdx.x, lane = tid & 31, w = tid >> 5;
    __shared__ float sl[KE];
    const float* cr = context + (long)b * Hd;
    {
        const float* wg = W_gate + (long)w * Hd;
        float s = 0.f;
        for (int h = lane; h < Hd; h += 32) s += cr[h] * wg[h];
        #pragma unroll
        for (int o = 16; o; o >>= 1) s += __shfl_xor_sync(0xffffffffu, s, o);
        if (lane == 0) sl[w] = s + b_gate[w];
    }
    __syncthreads();
    float lg[KE], m = -1e30f;
    #pragma unroll
    for (int k = 0; k < KE; k++) { lg[k] = sl[k]; m = fmaxf(m, lg[k]); }
    float e[KE], sum = 0.f;
    #pragma unroll
    for (int k = 0; k < KE; k++) { e[k] = expf(lg[k] - m); sum += e[k]; }
    float inv = 1.f / sum;
    if (tid < KE) {
        logits_out[(long)b * KE + tid] = lg[tid];
        gt_out[(long)b * KE + tid]     = e[tid] * inv;
    }
    const float* hb = h_new + (long)b * KE * Hd;
    #pragma unroll
    for (int t = 0; t < 4; t++) {
        int h = tid + t * 256;
        float acc = 0.f;
        #pragma unroll
        for (int k = 0; k < KE; k++) acc += e[k] * inv * hb[(long)k * Hd + h];
        mixed[(long)b * Hd + h] = acc;
    }
}

// ---------------- host orchestration -----------------------------------------
static void launch_mma(const float* A, const float* Bm, const float* bias, float* C,
                       int M, int N, int Kd, int lda, int ldb, int ldc,
                       int batch, long aBat, long bBat, long cBat, long biasBat)
{
    dim3 grid(N / 128, M / 128, batch);
    mma_tn<<<grid, 256, SMEMB>>>(A, Bm, bias, C, Kd, lda, ldb, ldc,
                                 aBat, bBat, cBat, biasBat);
}

extern "C" void kernel_launch(void* const* d_in, const int* in_sizes, int n_in,
                              void* d_out, int out_size)
{
    const float* x_t     = (const float*)d_in[0];
    const float* h_prev  = (const float*)d_in[1];
    const float* W_ih    = (const float*)d_in[2];
    const float* W_hh    = (const float*)d_in[3];
    const float* b_ih    = (const float*)d_in[4];
    const float* b_hh    = (const float*)d_in[5];
    const float* ln_g    = (const float*)d_in[6];
    const float* ln_b    = (const float*)d_in[7];
    const float* Wq_proj = (const float*)d_in[8];
    const float* bq_proj = (const float*)d_in[9];
    const float* W_q     = (const float*)d_in[10];
    const float* W_k     = (const float*)d_in[11];
    const float* W_v     = (const float*)d_in[12];
    const float* b_q     = (const float*)d_in[13];
    const float* b_k     = (const float*)d_in[14];
    const float* b_v     = (const float*)d_in[15];
    const float* W_o     = (const float*)d_in[16];
    const float* b_o     = (const float*)d_in[17];
    const float* aln_g   = (const float*)d_in[18];
    const float* aln_b   = (const float*)d_in[19];
    const float* W_gate  = (const float*)d_in[20];
    const float* b_gate  = (const float*)d_in[21];
    const float* W_read  = (const float*)d_in[22];
    const float* b_read  = (const float*)d_in[23];

    float* out    = (float*)d_out;
    float* h_new  = out;                                   // (B,K,H)
    float* y_hat  = out + (long)Bsz * KE * Hd;             // (B,O)
    float* g_t    = y_hat + (long)Bsz * Oo;                // (B,K)
    float* logits = g_t + (long)Bsz * KE;                  // (B,K)

    float *gi, *gh, *query, *qm, *kmat, *vmat, *ctx, *attnout, *contextb, *mixed;
    cudaGetSymbolAddress((void**)&gi, g_gi);
    cudaGetSymbolAddress((void**)&gh, g_gh);
    cudaGetSymbolAddress((void**)&query, g_query);
    cudaGetSymbolAddress((void**)&qm, g_q);
    cudaGetSymbolAddress((void**)&kmat, g_kmat);
    cudaGetSymbolAddress((void**)&vmat, g_vmat);
    cudaGetSymbolAddress((void**)&ctx, g_ctx);
    cudaGetSymbolAddress((void**)&attnout, g_attnout);
    cudaGetSymbolAddress((void**)&contextb, g_context);
    cudaGetSymbolAddress((void**)&mixed, g_mixed);

    cudaFuncSetAttribute(mma_tn, cudaFuncAttributeMaxDynamicSharedMemorySize, SMEMB);

    // 1) gi = x_t @ W_ih^T + b_ih          (4096 x 24576 x 512)
    launch_mma(x_t, W_ih, b_ih, gi, Bsz, KE * 3 * Hd, Din,
               Din, Din, KE * 3 * Hd, 1, 0, 0, 0, 0);
    // 2) gh[k] = h_prev[:,k,:] @ W_hh[k]^T + b_hh[k]   (batched over K)
    launch_mma(h_prev, W_hh, b_hh, gh, Bsz, 3 * Hd, Hd,
               KE * Hd, Hd, KE * 3 * Hd, KE,
               (long)Hd, (long)3 * Hd * Hd, (long)3 * Hd, (long)3 * Hd);
    // 3) GRU pointwise + per-expert LN -> h_new (into d_out)
    gru_ln_kernel<<<Bsz * KE, 256>>>(gi, gh, h_prev, ln_g, ln_b, h_new);
    // 4) query = x_t @ Wq_proj^T + bq_proj
    launch_mma(x_t, Wq_proj, bq_proj, query, Bsz, Hd, Din,
               Din, Din, Hd, 1, 0, 0, 0, 0);
    // 5) q = query @ W_q^T + b_q
    launch_mma(query, W_q, b_q, qm, Bsz, Hd, Hd, Hd, Hd, Hd, 1, 0, 0, 0, 0);
    // 6) kmat = h_new @ W_k^T + b_k     (32768 x 1024 x 1024)
    launch_mma(h_new, W_k, b_k, kmat, Bsz * KE, Hd, Hd, Hd, Hd, Hd, 1, 0, 0, 0, 0);
    // 7) vmat = h_new @ W_v^T + b_v
    launch_mma(h_new, W_v, b_v, vmat, Bsz * KE, Hd, Hd, Hd, Hd, Hd, 1, 0, 0, 0, 0);
    // 8) attention -> ctx
    attn_kernel<<<Bsz * NHh, 256>>>(qm, kmat, vmat, ctx);
    // 9) attn_out = ctx @ W_o^T + b_o
    launch_mma(ctx, W_o, b_o, attnout, Bsz, Hd, Hd, Hd, Hd, Hd, 1, 0, 0, 0, 0);
    // 10) context = LN(query + attn_out)
    add_ln_kernel<<<Bsz, 256>>>(query, attnout, aln_g, aln_b, contextb);
    // 11) gate logits + softmax + mix
    gate_mix_kernel<<<Bsz, 256>>>(contextb, W_gate, b_gate, h_new, logits, g_t, mixed);
    // 12) y_hat = mixed @ W_read^T + b_read
    launch_mma(mixed, W_read, b_read, y_hat, Bsz, Oo, Hd, Hd, Hd, Oo, 1, 0, 0, 0, 0);
}

// round 9
// speedup vs baseline: 2.9822x; 1.1218x over previous
#include <cuda_runtime.h>
#include <math.h>
#include <stdint.h>

#define Bsz  4096
#define Din  512
#define Hd   1024
#define KE   8
#define Oo   256
#define NHh  4
#define HDim 256
#define EPSv 1e-5f

// ---------------- scratch (device globals; no allocations allowed) ----------
__device__ float g_gi[(size_t)Bsz * KE * 3 * Hd];   // (B, K, 3H)
__device__ float g_gh[(size_t)Bsz * KE * 3 * Hd];   // (B, K, 3H)
__device__ float g_query[(size_t)Bsz * Hd];
__device__ float g_q[(size_t)Bsz * Hd];
__device__ float g_kmat[(size_t)Bsz * KE * Hd];
__device__ float g_vmat[(size_t)Bsz * KE * Hd];
__device__ float g_ctx[(size_t)Bsz * Hd];
__device__ float g_attnout[(size_t)Bsz * Hd];
__device__ float g_context[(size_t)Bsz * Hd];
__device__ float g_mixed[(size_t)Bsz * Hd];

// ---------------- helpers ----------------------------------------------------
__device__ __forceinline__ float to_tf32(float x) {
    float r; asm("cvt.rna.tf32.f32 %0, %1;" : "=f"(r) : "f"(x)); return r;
}
__device__ __forceinline__ uint32_t f2t(float x) {
    return __float_as_uint(to_tf32(x));
}
__device__ __forceinline__ void mma16n8k8(float* c, const uint32_t* a, const uint32_t* b) {
    asm volatile("mma.sync.aligned.m16n8k8.row.col.f32.tf32.tf32.f32 "
        "{%0,%1,%2,%3}, {%4,%5,%6,%7}, {%8,%9}, {%0,%1,%2,%3};"
        : "+f"(c[0]), "+f"(c[1]), "+f"(c[2]), "+f"(c[3])
        : "r"(a[0]), "r"(a[1]), "r"(a[2]), "r"(a[3]), "r"(b[0]), "r"(b[1]));
}
__device__ __forceinline__ uint32_t smem_u32(const void* p) {
    uint32_t a;
    asm("{ .reg .u64 t; cvta.to.shared.u64 t, %1; cvt.u32.u64 %0, t; }" : "=r"(a) : "l"(p));
    return a;
}
__device__ __forceinline__ void cp_async16(uint32_t dst, const void* src) {
    asm volatile("cp.async.cg.shared.global [%0], [%1], 16;" :: "r"(dst), "l"(src));
}
#define CP_COMMIT()  asm volatile("cp.async.commit_group;" ::: "memory")
#define CP_WAIT(n)   asm volatile("cp.async.wait_group %0;" :: "n"(n) : "memory")

// ================= tf32 mma.sync TN GEMM (cp.async 3-stage) ==================
// C[m,n] = sum_k A[m,k]*B[n,k] + bias[n]
// Block 128x128, K-chunk 32, 256 threads (8 warps: 2M x 4N, warp tile 64x32).
// Smem stage: A 128x32 + B 128x32, stride 36 floats; 3 stages, 2 CTAs/SM.
// Invariant: EVERY loop iteration commits exactly one cp.async group (empty in
// the tail), so at the top of iteration c the newest group is G(c+1) and
// wait_group(1) provably retires chunk c's group — including the last chunk.
#define STG_W   4608                        // 128*36 words per matrix-stage
#define STAGE_W (2 * STG_W)                 // A + B per stage
#define NSTAGE  3
#define SMEMW   (NSTAGE * STAGE_W)
#define SMEMB   (SMEMW * 4)                 // 110592 bytes

__global__ __launch_bounds__(256, 2)
void mma_tn(const float* __restrict__ A, const float* __restrict__ Bm,
            const float* __restrict__ bias, float* __restrict__ C,
            int Kd, int lda, int ldb, int ldc,
            long aBat, long bBat, long cBat, long biasBat)
{
    extern __shared__ float smf[];
    const int tid  = threadIdx.x;
    const int wid  = tid >> 5;
    const int lane = tid & 31;
    const int warpM = wid & 1;        // 0..1  (64 rows each)
    const int warpN = wid >> 1;       // 0..3  (32 cols each)
    const int r = lane >> 2;          // 0..7
    const int q = lane & 3;           // 0..3

    const int bz = blockIdx.z;
    A  += (long)bz * aBat;
    Bm += (long)bz * bBat;
    C  += (long)bz * cBat;
    const float* biasp = bias ? bias + (long)bz * biasBat : nullptr;

    const int rowBase = blockIdx.y * 128;
    const int colBase = blockIdx.x * 128;

    const int lrow = tid >> 3;        // 0..31 -> covers 128 rows via i*32
    const int lc4  = (tid & 7) * 4;   // 0,4,...,28

    const uint32_t smb = smem_u32(smf);

    // issue cp.async for one 32-wide K chunk into stage s (one group)
    auto issue_chunk = [&](int k0, int s) {
        const uint32_t as = smb + (s * STAGE_W) * 4;
        const uint32_t bs = as + STG_W * 4;
        const uint32_t soff = (lrow * 36 + lc4) * 4;
        #pragma unroll
        for (int i = 0; i < 4; i++) {
            int row = lrow + i * 32;
            cp_async16(as + soff + i * (32 * 36 * 4),
                       A + (long)(rowBase + row) * lda + k0 + lc4);
            cp_async16(bs + soff + i * (32 * 36 * 4),
                       Bm + (long)(colBase + row) * ldb + k0 + lc4);
        }
        CP_COMMIT();
    };

    float acc[4][4][4];
    #pragma unroll
    for (int mt = 0; mt < 4; mt++)
        #pragma unroll
        for (int nt = 0; nt < 4; nt++)
            #pragma unroll
            for (int j = 0; j < 4; j++) acc[mt][nt][j] = 0.0f;

    const int NC = Kd >> 5;

    // prologue: prefetch NSTAGE-1 chunks (chunks 0 and 1 -> groups G0, G1)
    issue_chunk(0, 0);
    if (NC > 1) issue_chunk(32, 1);
    else        CP_COMMIT();          // keep group-count invariant for NC==1

    for (int c = 0; c < NC; c++) {
        const int s = c % NSTAGE;
        CP_WAIT(NSTAGE - 2);          // newest group is G(c+1) -> G(c) retired
        __syncthreads();

        const float* as = smf + s * STAGE_W + (warpM * 64) * 36;
        const float* bs = smf + s * STAGE_W + STG_W + (warpN * 32) * 36;

        #pragma unroll
        for (int ks = 0; ks < 4; ks++) {
            const int k0 = ks * 8;
            uint32_t afr[4][4], bfr[4][2];
            #pragma unroll
            for (int mt = 0; mt < 4; mt++) {
                const float* ap = as + (mt * 16 + r) * 36 + k0 + q;
                afr[mt][0] = f2t(ap[0]);
                afr[mt][1] = f2t(ap[8 * 36]);
                afr[mt][2] = f2t(ap[4]);
                afr[mt][3] = f2t(ap[8 * 36 + 4]);
            }
            #pragma unroll
            for (int nt = 0; nt < 4; nt++) {
                const float* bp = bs + (nt * 8 + r) * 36 + k0 + q;
                bfr[nt][0] = f2t(bp[0]);
                bfr[nt][1] = f2t(bp[4]);
            }
            #pragma unroll
            for (int mt = 0; mt < 4; mt++)
                #pragma unroll
                for (int nt = 0; nt < 4; nt++)
                    mma16n8k8(acc[mt][nt], afr[mt], bfr[nt]);
        }

        // issue next prefetch (or an EMPTY group to keep counts uniform)
        if (c + NSTAGE - 1 < NC)
            issue_chunk((c + NSTAGE - 1) * 32, (c + NSTAGE - 1) % NSTAGE);
        else
            CP_COMMIT();
        __syncthreads();
    }

    // ---- epilogue: acc -> C (+bias) ----
    #pragma unroll
    for (int mt = 0; mt < 4; mt++) {
        const int row = rowBase + warpM * 64 + mt * 16 + r;
        #pragma unroll
        for (int nt = 0; nt < 4; nt++) {
            const int col = colBase + warpN * 32 + nt * 8 + q * 2;
            float b0 = 0.f, b1 = 0.f;
            if (biasp) { b0 = biasp[col]; b1 = biasp[col + 1]; }
            float2 v0, v1;
            v0.x = acc[mt][nt][0] + b0; v0.y = acc[mt][nt][1] + b1;
            v1.x = acc[mt][nt][2] + b0; v1.y = acc[mt][nt][3] + b1;
            *(float2*)(C + (long)row * ldc + col)       = v0;
            *(float2*)(C + (long)(row + 8) * ldc + col) = v1;
        }
    }
}

// ---------------- GRU pointwise + per-expert LayerNorm -----------------------
__global__ void gru_ln_kernel(const float* __restrict__ gi, const float* __restrict__ gh,
                              const float* __restrict__ h_prev,
                              const float* __restrict__ ln_g, const float* __restrict__ ln_b,
                              float* __restrict__ h_new)
{
    const int bk = blockIdx.x;
    const int k  = bk & (KE - 1);
    const long giBase = (long)bk * (3 * Hd);
    const long hBase  = (long)bk * Hd;
    const float* gir = gi + giBase;
    const float* ghr = gh + giBase;
    const float* hp  = h_prev + hBase;

    float vals[4];
    float s = 0.f, ss = 0.f;
    #pragma unroll
    for (int t = 0; t < 4; t++) {
        int h = threadIdx.x + t * 256;
        float ir = gir[h],           hr = ghr[h];
        float iz = gir[Hd + h],      hz = ghr[Hd + h];
        float inn = gir[2 * Hd + h], hn = ghr[2 * Hd + h];
        float r = 1.f / (1.f + expf(-(ir + hr)));
        float z = 1.f / (1.f + expf(-(iz + hz)));
        float n = tanhf(inn + r * hn);
        float hv = (1.f - z) * n + z * hp[h];
        vals[t] = hv; s += hv; ss += hv * hv;
    }
    __shared__ float red[16];
    #pragma unroll
    for (int o = 16; o; o >>= 1) {
        s  += __shfl_xor_sync(0xffffffffu, s, o);
        ss += __shfl_xor_sync(0xffffffffu, ss, o);
    }
    int w = threadIdx.x >> 5;
    if ((threadIdx.x & 31) == 0) { red[w] = s; red[8 + w] = ss; }
    __syncthreads();
    s = 0.f; ss = 0.f;
    #pragma unroll
    for (int i = 0; i < 8; i++) { s += red[i]; ss += red[8 + i]; }
    float mean = s * (1.f / Hd);
    float var  = ss * (1.f / Hd) - mean * mean;
    float rstd = rsqrtf(var + EPSv);
    #pragma unroll
    for (int t = 0; t < 4; t++) {
        int h = threadIdx.x + t * 256;
        h_new[hBase + h] = (vals[t] - mean) * rstd * ln_g[k * Hd + h] + ln_b[k * Hd + h];
    }
}

// ---------------- attention over K=8 expert states ---------------------------
__global__ void attn_kernel(const float* __restrict__ q, const float* __restrict__ kmat,
                            const float* __restrict__ vmat, float* __restrict__ ctx)
{
    const int b = blockIdx.x >> 2;
    const int n = blockIdx.x & 3;
    const int tid = threadIdx.x;
    const int lane = tid & 31, w = tid >> 5;
    __shared__ float sc[KE];
    const float* qp = q + (long)b * Hd + n * HDim;
    {
        const float* kp = kmat + (long)b * KE * Hd + (long)w * Hd + n * HDim;
        float s = 0.f;
        #pragma unroll
        for (int d = lane; d < HDim; d += 32) s += qp[d] * kp[d];
        #pragma unroll
        for (int o = 16; o; o >>= 1) s += __shfl_xor_sync(0xffffffffu, s, o);
        if (lane == 0) sc[w] = s * (1.0f / 16.0f);
    }
    __syncthreads();
    float e[KE], m = -1e30f;
    #pragma unroll
    for (int k = 0; k < KE; k++) m = fmaxf(m, sc[k]);
    float sum = 0.f;
    #pragma unroll
    for (int k = 0; k < KE; k++) { e[k] = expf(sc[k] - m); sum += e[k]; }
    float inv = 1.f / sum;
    float acc = 0.f;
    const float* vb = vmat + (long)b * KE * Hd + n * HDim + tid;
    #pragma unroll
    for (int k = 0; k < KE; k++) acc += e[k] * inv * vb[(long)k * Hd];
    ctx[(long)b * Hd + n * HDim + tid] = acc;
}

// ---------------- residual add + LayerNorm -----------------------------------
__global__ void add_ln_kernel(const float* __restrict__ a, const float* __restrict__ bvec,
                              const float* __restrict__ g, const float* __restrict__ be,
                              float* __restrict__ out)
{
    const int b = blockIdx.x;
    const long base = (long)b * Hd;
    float vals[4]; float s = 0.f, ss = 0.f;
    #pragma unroll
    for (int t = 0; t < 4; t++) {
        int h = threadIdx.x + t * 256;
        float v = a[base + h] + bvec[base + h];
        vals[t] = v; s += v; ss += v * v;
    }
    __shared__ float red[16];
    #pragma unroll
    for (int o = 16; o; o >>= 1) {
        s  += __shfl_xor_sync(0xffffffffu, s, o);
        ss += __shfl_xor_sync(0xffffffffu, ss, o);
    }
    int w = threadIdx.x >> 5;
    if ((threadIdx.x & 31) == 0) { red[w] = s; red[8 + w] = ss; }
    __syncthreads();
    s = 0.f; ss = 0.f;
    #pragma unroll
    for (int i = 0; i < 8; i++) { s += red[i]; ss += red[8 + i]; }
    float mean = s * (1.f / Hd);
    float rstd = rsqrtf(ss * (1.f / Hd) - mean * mean + EPSv);
    #pragma unroll
    for (int t = 0; t < 4; t++) {
        int h = threadIdx.x + t * 256;
        out[base + h] = (vals[t] - mean) * rstd * g[h] + be[h];
    }
}

// ---------------- gate logits + softmax + expert mix -------------------------
__global__ void gate_mix_kernel(const float* __restrict__ context, const float* __restrict__ W_gate,
                                const float* __restrict__ b_gate, const float* __restrict__ h_new,
                                float* __restrict__ logits_out, float* __restrict__ gt_out,
                                float* __restrict__ mixed)
{
    const int b = blockIdx.x;
    const int tid = threadIdx.x, lane = tid & 31, w = tid >> 5;
    __shared__ float sl[KE];
    const float* cr = context + (long)b * Hd;
    {
        const float* wg = W_gate + (long)w * Hd;
        float s = 0.f;
        for (int h = lane; h < Hd; h += 32) s += cr[h] * wg[h];
        #pragma unroll
        for (int o = 16; o; o >>= 1) s += __shfl_xor_sync(0xffffffffu, s, o);
        if (lane == 0) sl[w] = s + b_gate[w];
    }
    __syncthreads();
    float lg[KE], m = -1e30f;
    #pragma unroll
    for (int k = 0; k < KE; k++) { lg[k] = sl[k]; m = fmaxf(m, lg[k]); }
    float e[KE], sum = 0.f;
    #pragma unroll
    for (int k = 0; k < KE; k++) { e[k] = expf(lg[k] - m); sum += e[k]; }
    float inv = 1.f / sum;
    if (tid < KE) {
        logits_out[(long)b * KE + tid] = lg[tid];
        gt_out[(long)b * KE + tid]     = e[tid] * inv;
    }
    const float* hb = h_new + (long)b * KE * Hd;
    #pragma unroll
    for (int t = 0; t < 4; t++) {
        int h = tid + t * 256;
        float acc = 0.f;
        #pragma unroll
        for (int k = 0; k < KE; k++) acc += e[k] * inv * hb[(long)k * Hd + h];
        mixed[(long)b * Hd + h] = acc;
    }
}

// ---------------- host orchestration -----------------------------------------
static void launch_mma(const float* A, const float* Bm, const float* bias, float* C,
                       int M, int N, int Kd, int lda, int ldb, int ldc,
                       int batch, long aBat, long bBat, long cBat, long biasBat)
{
    dim3 grid(N / 128, M / 128, batch);
    mma_tn<<<grid, 256, SMEMB>>>(A, Bm, bias, C, Kd, lda, ldb, ldc,
                                 aBat, bBat, cBat, biasBat);
}

extern "C" void kernel_launch(void* const* d_in, const int* in_sizes, int n_in,
                              void* d_out, int out_size)
{
    const float* x_t     = (const float*)d_in[0];
    const float* h_prev  = (const float*)d_in[1];
    const float* W_ih    = (const float*)d_in[2];
    const float* W_hh    = (const float*)d_in[3];
    const float* b_ih    = (const float*)d_in[4];
    const float* b_hh    = (const float*)d_in[5];
    const float* ln_g    = (const float*)d_in[6];
    const float* ln_b    = (const float*)d_in[7];
    const float* Wq_proj = (const float*)d_in[8];
    const float* bq_proj = (const float*)d_in[9];
    const float* W_q     = (const float*)d_in[10];
    const float* W_k     = (const float*)d_in[11];
    const float* W_v     = (const float*)d_in[12];
    const float* b_q     = (const float*)d_in[13];
    const float* b_k     = (const float*)d_in[14];
    const float* b_v     = (const float*)d_in[15];
    const float* W_o     = (const float*)d_in[16];
    const float* b_o     = (const float*)d_in[17];
    const float* aln_g   = (const float*)d_in[18];
    const float* aln_b   = (const float*)d_in[19];
    const float* W_gate  = (const float*)d_in[20];
    const float* b_gate  = (const float*)d_in[21];
    const float* W_read  = (const float*)d_in[22];
    const float* b_read  = (const float*)d_in[23];

    float* out    = (float*)d_out;
    float* h_new  = out;                                   // (B,K,H)
    float* y_hat  = out + (long)Bsz * KE * Hd;             // (B,O)
    float* g_t    = y_hat + (long)Bsz * Oo;                // (B,K)
    float* logits = g_t + (long)Bsz * KE;                  // (B,K)

    float *gi, *gh, *query, *qm, *kmat, *vmat, *ctx, *attnout, *contextb, *mixed;
    cudaGetSymbolAddress((void**)&gi, g_gi);
    cudaGetSymbolAddress((void**)&gh, g_gh);
    cudaGetSymbolAddress((void**)&query, g_query);
    cudaGetSymbolAddress((void**)&qm, g_q);
    cudaGetSymbolAddress((void**)&kmat, g_kmat);
    cudaGetSymbolAddress((void**)&vmat, g_vmat);
    cudaGetSymbolAddress((void**)&ctx, g_ctx);
    cudaGetSymbolAddress((void**)&attnout, g_attnout);
    cudaGetSymbolAddress((void**)&contextb, g_context);
    cudaGetSymbolAddress((void**)&mixed, g_mixed);

    cudaFuncSetAttribute(mma_tn, cudaFuncAttributeMaxDynamicSharedMemorySize, SMEMB);

    // 1) gi = x_t @ W_ih^T + b_ih          (4096 x 24576 x 512)
    launch_mma(x_t, W_ih, b_ih, gi, Bsz, KE * 3 * Hd, Din,
               Din, Din, KE * 3 * Hd, 1, 0, 0, 0, 0);
    // 2) gh[k] = h_prev[:,k,:] @ W_hh[k]^T + b_hh[k]   (batched over K)
    launch_mma(h_prev, W_hh, b_hh, gh, Bsz, 3 * Hd, Hd,
               KE * Hd, Hd, KE * 3 * Hd, KE,
               (long)Hd, (long)3 * Hd * Hd, (long)3 * Hd, (long)3 * Hd);
    // 3) GRU pointwise + per-expert LN -> h_new (into d_out)
    gru_ln_kernel<<<Bsz * KE, 256>>>(gi, gh, h_prev, ln_g, ln_b, h_new);
    // 4) query = x_t @ Wq_proj^T + bq_proj
    launch_mma(x_t, Wq_proj, bq_proj, query, Bsz, Hd, Din,
               Din, Din, Hd, 1, 0, 0, 0, 0);
    // 5) q = query @ W_q^T + b_q
    launch_mma(query, W_q, b_q, qm, Bsz, Hd, Hd, Hd, Hd, Hd, 1, 0, 0, 0, 0);
    // 6) kmat = h_new @ W_k^T + b_k     (32768 x 1024 x 1024)
    launch_mma(h_new, W_k, b_k, kmat, Bsz * KE, Hd, Hd, Hd, Hd, Hd, 1, 0, 0, 0, 0);
    // 7) vmat = h_new @ W_v^T + b_v
    launch_mma(h_new, W_v, b_v, vmat, Bsz * KE, Hd, Hd, Hd, Hd, Hd, 1, 0, 0, 0, 0);
    // 8) attention -> ctx
    attn_kernel<<<Bsz * NHh, 256>>>(qm, kmat, vmat, ctx);
    // 9) attn_out = ctx @ W_o^T + b_o
    launch_mma(ctx, W_o, b_o, attnout, Bsz, Hd, Hd, Hd, Hd, Hd, 1, 0, 0, 0, 0);
    // 10) context = LN(query + attn_out)
    add_ln_kernel<<<Bsz, 256>>>(query, attnout, aln_g, aln_b, contextb);
    // 11) gate logits + softmax + mix
    gate_mix_kernel<<<Bsz, 256>>>(contextb, W_gate, b_gate, h_new, logits, g_t, mixed);
    // 12) y_hat = mixed @ W_read^T + b_read
    launch_mma(mixed, W_read, b_read, y_hat, Bsz, Oo, Hd, Hd, Hd, Oo, 1, 0, 0, 0, 0);
}